// round 1
// baseline (speedup 1.0000x reference)
#include <cuda_runtime.h>
#include <cuda_bf16.h>
#include <cstdint>

// ConceptEmb restructured:
//  K0 prep:       pack W = [qW;kW] (128 feat x 128 dim) into bf16x2 pairs + bias.
//  K1 precompute: QK_tab[v][f] = (W @ e_v + bias), f<64 scaled by 1/sqrt(H)=0.125,
//                 stored bf16 (scores path tolerates bf16: logits ~1e-4).
//  K2 main:       per set (warp): gather QK rows, scores s_ij = Q_i . K_j (HFMA2),
//                 softmax over ALL j for unmasked i only (reference's kmask=m*m^T
//                 is exactly 0 on unmasked query rows), g_j = sum_i w_i p_ij,
//                 pooled = sum_j g_j * emb[id_j] in fp32.

#define V_MAX   50000
#define D_DIM   128
#define NSET    32

__device__ __nv_bfloat16 g_qk[(size_t)V_MAX * 128];  // [v][f] f=0..63: Q*0.125, 64..127: K
__device__ uint32_t      g_wp[128 * 64];             // [d][fpair] bf16x2 (W[f0][d], W[f1][d])
__device__ uint32_t      g_bias[64];                 // bf16x2 bias pairs (pre-scaled)

static __device__ __forceinline__ __nv_bfloat162 b2(uint32_t u) {
    return *reinterpret_cast<__nv_bfloat162*>(&u);
}
static __device__ __forceinline__ uint32_t u2(__nv_bfloat162 h) {
    return *reinterpret_cast<uint32_t*>(&h);
}

// ---------------------------------------------------------------- K0: prep W
__global__ void prep_kernel(const float* __restrict__ qW, const float* __restrict__ qb,
                            const float* __restrict__ kW, const float* __restrict__ kb) {
    int idx = blockIdx.x * blockDim.x + threadIdx.x;
    if (idx < 128 * 64) {
        int d = idx >> 6, fp = idx & 63;
        int f0 = fp * 2, f1 = f0 + 1;
        float w0 = (f0 < 64) ? qW[f0 * 128 + d] : kW[(f0 - 64) * 128 + d];
        float w1 = (f1 < 64) ? qW[f1 * 128 + d] : kW[(f1 - 64) * 128 + d];
        __nv_bfloat162 p = __floats2bfloat162_rn(w0, w1);
        g_wp[d * 64 + fp] = u2(p);
    }
    if (idx < 64) {
        int f0 = idx * 2, f1 = f0 + 1;
        float b0 = ((f0 < 64) ? qb[f0] : kb[f0 - 64]) * ((f0 < 64) ? 0.125f : 1.0f);
        float b1 = ((f1 < 64) ? qb[f1] : kb[f1 - 64]) * ((f1 < 64) ? 0.125f : 1.0f);
        __nv_bfloat162 p = __floats2bfloat162_rn(b0, b1);
        g_bias[idx] = u2(p);
    }
}

// ------------------------------------------------ K1: QK table (64 vocab rows/CTA)
// Block tile 64 v-rows x 128 feats, K=128 contraction in 2 W-halves (smem <= 48KB).
// Thread tile 8v x 8f (4 bf16x2 fpairs), HFMA2 accumulation.
__global__ void __launch_bounds__(128) qk_precompute(const float* __restrict__ emb, int V) {
    __shared__ __nv_bfloat16 Es[128 * 72];  // [d][v], row stride 72 (pad, 144B 16B-aligned)
    __shared__ uint32_t      Ws[64 * 64];   // [dh][fpair] for current half

    int t  = threadIdx.x;
    int v0 = blockIdx.x * 64;

    // Load E tile (64 rows x 128 dims), transpose into Es[d][v] as bf16
    #pragma unroll 4
    for (int r = 0; r < 64; r++) {
        int v = v0 + r;
        float val = (v < V) ? emb[(size_t)v * 128 + t] : 0.0f;
        Es[t * 72 + r] = __float2bfloat16(val);
    }

    int fpt = t & 15, vt = t >> 4;
    uint32_t acc[8][4];
    #pragma unroll
    for (int a = 0; a < 8; a++)
        #pragma unroll
        for (int b = 0; b < 4; b++) acc[a][b] = 0u;  // bf16x2 zero

    for (int pass = 0; pass < 2; pass++) {
        __syncthreads();
        #pragma unroll
        for (int i = 0; i < 32; i++)
            Ws[i * 128 + t] = g_wp[pass * 4096 + i * 128 + t];
        __syncthreads();

        #pragma unroll 2
        for (int dh = 0; dh < 64; dh++) {
            int d = pass * 64 + dh;
            uint4 ev = *reinterpret_cast<const uint4*>(Es + d * 72 + vt * 8);
            uint32_t e2[8];
            e2[0] = __byte_perm(ev.x, 0, 0x1010); e2[1] = __byte_perm(ev.x, 0, 0x3232);
            e2[2] = __byte_perm(ev.y, 0, 0x1010); e2[3] = __byte_perm(ev.y, 0, 0x3232);
            e2[4] = __byte_perm(ev.z, 0, 0x1010); e2[5] = __byte_perm(ev.z, 0, 0x3232);
            e2[6] = __byte_perm(ev.w, 0, 0x1010); e2[7] = __byte_perm(ev.w, 0, 0x3232);
            uint4 wv = *reinterpret_cast<const uint4*>(Ws + dh * 64 + fpt * 4);
            uint32_t w2[4] = {wv.x, wv.y, wv.z, wv.w};
            #pragma unroll
            for (int a = 0; a < 8; a++)
                #pragma unroll
                for (int b = 0; b < 4; b++)
                    acc[a][b] = u2(__hfma2(b2(e2[a]), b2(w2[b]), b2(acc[a][b])));
        }
    }

    __nv_bfloat162 sc = __float2bfloat162_rn((fpt < 8) ? 0.125f : 1.0f);
    uint32_t bb[4];
    #pragma unroll
    for (int b = 0; b < 4; b++) bb[b] = g_bias[fpt * 4 + b];

    #pragma unroll
    for (int a = 0; a < 8; a++) {
        int vr = v0 + vt * 8 + a;
        if (vr < V) {
            uint4 st;
            st.x = u2(__hfma2(b2(acc[a][0]), sc, b2(bb[0])));
            st.y = u2(__hfma2(b2(acc[a][1]), sc, b2(bb[1])));
            st.z = u2(__hfma2(b2(acc[a][2]), sc, b2(bb[2])));
            st.w = u2(__hfma2(b2(acc[a][3]), sc, b2(bb[3])));
            reinterpret_cast<uint4*>(g_qk + (size_t)vr * 128)[fpt] = st;
        }
    }
}

// ------------------------------------------------ K2: main (1 warp = 1 set)
__global__ void __launch_bounds__(128) concept_kernel(
    const int*   __restrict__ ids,
    const float* __restrict__ mask,
    const float* __restrict__ times,
    const float* __restrict__ emb,
    const float* __restrict__ theta,
    const float* __restrict__ mu,
    float*       __restrict__ out,
    int nsets)
{
    __shared__ uint32_t qs[4][32 * 36];  // per-warp Q rows, row stride 36 u32 (144B)

    const unsigned FULL = 0xffffffffu;
    int warp = threadIdx.x >> 5, lane = threadIdx.x & 31;
    int set  = blockIdx.x * 4 + warp;
    if (set >= nsets) return;

    int   base = set * NSET + lane;
    int   idv  = ids[base];
    float mk   = mask[base];
    float tm   = times[set];
    float th   = theta[idv];
    float muv  = mu[idv];
    float sig  = 1.0f / (1.0f + __expf(-(th - muv * tm)));
    float w    = sig * mk;                       // 0 exactly when mask==0
    unsigned act = __ballot_sync(FULL, mk > 0.5f);

    // K row of this lane's concept -> registers (64 bf16 = 32 bf16x2)
    uint32_t kreg[32];
    {
        const uint4* kp = reinterpret_cast<const uint4*>(g_qk + (size_t)idv * 128 + 64);
        #pragma unroll
        for (int c = 0; c < 8; c++) {
            uint4 x = kp[c];
            kreg[4*c] = x.x; kreg[4*c+1] = x.y; kreg[4*c+2] = x.z; kreg[4*c+3] = x.w;
        }
    }
    // Q row -> shared (broadcast-read in the i-loop)
    {
        const uint4* qp = reinterpret_cast<const uint4*>(g_qk + (size_t)idv * 128);
        uint4* myq = reinterpret_cast<uint4*>(&qs[warp][lane * 36]);
        #pragma unroll
        for (int c = 0; c < 8; c++) myq[c] = qp[c];
    }
    __syncwarp();

    // g_j = sum over unmasked i of w_i * softmax_i(s)_j   (lane j holds g_j)
    float g = 0.0f;
    unsigned a = act;
    while (a) {
        int i = __ffs(a) - 1;
        a &= a - 1;
        float wi = __shfl_sync(FULL, w, i);

        const uint4* qrow = reinterpret_cast<const uint4*>(&qs[warp][i * 36]);
        __nv_bfloat162 acc0 = __float2bfloat162_rn(0.0f);
        __nv_bfloat162 acc1 = __float2bfloat162_rn(0.0f);
        #pragma unroll
        for (int c = 0; c < 8; c += 2) {
            uint4 q0 = qrow[c];
            acc0 = __hfma2(b2(kreg[4*c+0]), b2(q0.x), acc0);
            acc1 = __hfma2(b2(kreg[4*c+1]), b2(q0.y), acc1);
            acc0 = __hfma2(b2(kreg[4*c+2]), b2(q0.z), acc0);
            acc1 = __hfma2(b2(kreg[4*c+3]), b2(q0.w), acc1);
            uint4 q1 = qrow[c + 1];
            acc0 = __hfma2(b2(kreg[4*c+4]), b2(q1.x), acc0);
            acc1 = __hfma2(b2(kreg[4*c+5]), b2(q1.y), acc1);
            acc0 = __hfma2(b2(kreg[4*c+6]), b2(q1.z), acc0);
            acc1 = __hfma2(b2(kreg[4*c+7]), b2(q1.w), acc1);
        }
        float s = __bfloat162float(__low2bfloat16(acc0)) + __bfloat162float(__high2bfloat16(acc0))
                + __bfloat162float(__low2bfloat16(acc1)) + __bfloat162float(__high2bfloat16(acc1));

        // warp softmax over j (ALL 32 keys — faithful to reference's kmask quirk)
        float m = s;
        #pragma unroll
        for (int off = 16; off > 0; off >>= 1)
            m = fmaxf(m, __shfl_xor_sync(FULL, m, off));
        float e = __expf(s - m);
        float den = e;
        #pragma unroll
        for (int off = 16; off > 0; off >>= 1)
            den += __shfl_xor_sync(FULL, den, off);
        g = fmaf(__fdividef(wi, den), e, g);
    }

    // pooled_d = sum_j g_j * emb[id_j][d]  (fp32; lane owns 4 contiguous dims)
    float4 p = make_float4(0.f, 0.f, 0.f, 0.f);
    #pragma unroll 8
    for (int j = 0; j < NSET; j++) {
        float gj = __shfl_sync(FULL, g, j);
        int   vj = __shfl_sync(FULL, idv, j);
        float4 e4 = reinterpret_cast<const float4*>(emb + (size_t)vj * 128)[lane];
        p.x = fmaf(gj, e4.x, p.x);
        p.y = fmaf(gj, e4.y, p.y);
        p.z = fmaf(gj, e4.z, p.z);
        p.w = fmaf(gj, e4.w, p.w);
    }
    reinterpret_cast<float4*>(out + (size_t)set * 128)[lane] = p;
}

// ---------------------------------------------------------------- launch
extern "C" void kernel_launch(void* const* d_in, const int* in_sizes, int n_in,
                              void* d_out, int out_size) {
    const int*   ids   = (const int*)  d_in[0];
    const float* mask  = (const float*)d_in[1];
    const float* times = (const float*)d_in[2];
    const float* emb   = (const float*)d_in[3];
    const float* qW    = (const float*)d_in[4];
    const float* qb    = (const float*)d_in[5];
    const float* kW    = (const float*)d_in[6];
    const float* kb    = (const float*)d_in[7];
    const float* theta = (const float*)d_in[8];
    const float* mu    = (const float*)d_in[9];
    float* out = (float*)d_out;

    int nsets = in_sizes[2];              // B*LS
    int V     = in_sizes[8];              // vocab (theta_table elements)
    if (V > V_MAX) V = V_MAX;

    prep_kernel<<<32, 256>>>(qW, qb, kW, kb);
    qk_precompute<<<(V + 63) / 64, 128>>>(emb, V);
    concept_kernel<<<(nsets + 3) / 4, 128>>>(ids, mask, times, emb, theta, mu, out, nsets);
}

// round 4
// speedup vs baseline: 1.4499x; 1.4499x over previous
#include <cuda_runtime.h>
#include <cuda_bf16.h>
#include <cstdint>

// ConceptEmb, round 3 (resubmit of audited R2 design — infra failure last round):
//  K1 (qk_mma): fused W-prep + QK table GEMM via mma.sync m16n8k16 bf16.
//               g_qk[v] = [ (Wq e_v + qb)/8 | Wk e_v + kb ]  (bf16, 256B/row)
//               Also packs g_tm[v] = (theta[v], mu[v]).
//  K2 (concept_kernel): warp = set. Gather Q,K rows to smem, scores S = Q K^T
//               via 32 HMMA, row softmax in C-fragment layout (quad shfl),
//               column-sum g_j = sum_i w_i p_ij via stride-4 shfl reduce,
//               pooled = sum_j g_j emb[v_j] in fp32.

#define V_MAX 50000
#define NSET  32

__device__ __nv_bfloat16 g_qk[(size_t)V_MAX * 128];
__device__ float2        g_tm[V_MAX];

static __device__ __forceinline__ __nv_bfloat162 b2(uint32_t u) {
    return *reinterpret_cast<__nv_bfloat162*>(&u);
}
static __device__ __forceinline__ uint32_t u2(__nv_bfloat162 h) {
    return *reinterpret_cast<uint32_t*>(&h);
}
static __device__ __forceinline__ uint32_t s2u(const void* p) {
    return (uint32_t)__cvta_generic_to_shared(p);
}
static __device__ __forceinline__ void ldsm_x4(uint32_t& r0, uint32_t& r1,
                                               uint32_t& r2, uint32_t& r3, uint32_t a) {
    asm volatile("ldmatrix.sync.aligned.m8n8.x4.shared.b16 {%0,%1,%2,%3}, [%4];"
                 : "=r"(r0), "=r"(r1), "=r"(r2), "=r"(r3) : "r"(a));
}
static __device__ __forceinline__ void mma16816(float* c,
        const uint32_t* a, uint32_t b0, uint32_t b1) {
    asm volatile("mma.sync.aligned.m16n8k16.row.col.f32.bf16.bf16.f32 "
                 "{%0,%1,%2,%3}, {%4,%5,%6,%7}, {%8,%9}, {%0,%1,%2,%3};"
                 : "+f"(c[0]), "+f"(c[1]), "+f"(c[2]), "+f"(c[3])
                 : "r"(a[0]), "r"(a[1]), "r"(a[2]), "r"(a[3]), "r"(b0), "r"(b1));
}

// ------------------------------------------------------------------ K1
// CTA: 64 v-rows x 128 feats, K=128. 4 warps split N (32 feats each).
// smem (dynamic): Ws[128][68 u32] bf16 (stride 272B), Es[64][68 u32], Bs[128] f32.
__global__ void __launch_bounds__(128) qk_mma(
    const float* __restrict__ emb,
    const float* __restrict__ qW, const float* __restrict__ qb,
    const float* __restrict__ kW, const float* __restrict__ kb,
    const float* __restrict__ theta, const float* __restrict__ mu, int V)
{
    extern __shared__ uint32_t dsm[];
    uint32_t* Ws = dsm;                 // 128*68 u32
    uint32_t* Es = dsm + 128 * 68;      // 64*68 u32
    float*    Bs = (float*)(dsm + 128 * 68 + 64 * 68);  // 128 f32

    int tid = threadIdx.x, lane = tid & 31, w = tid >> 5;
    int v0 = blockIdx.x * 64;

    // W -> bf16 smem, rows [f][d]
    for (int i = tid; i < 64 * 128; i += 128) {
        int f = i >> 6, dp = i & 63;
        const float* src = (f < 64) ? (qW + f * 128) : (kW + (f - 64) * 128);
        float2 v = *reinterpret_cast<const float2*>(src + dp * 2);
        Ws[f * 68 + dp] = u2(__floats2bfloat162_rn(v.x, v.y));
    }
    Bs[tid] = (tid < 64) ? qb[tid] * 0.125f : kb[tid - 64];
    // E tile (64 rows)
    for (int i = tid; i < 32 * 128; i += 128) {
        int r = i >> 6, dp = i & 63;
        int v = v0 + r;
        float2 e = make_float2(0.f, 0.f);
        if (v < V) e = *reinterpret_cast<const float2*>(emb + (size_t)v * 128 + dp * 2);
        Es[r * 68 + dp] = u2(__floats2bfloat162_rn(e.x, e.y));
    }
    if (tid < 64 && (v0 + tid) < V)
        g_tm[v0 + tid] = make_float2(theta[v0 + tid], mu[v0 + tid]);
    __syncthreads();

    uint32_t es_base = s2u(Es);
    int g = lane >> 3;
    int q = lane & 3, r = lane >> 2;

    float acc[4][4][4];
    #pragma unroll
    for (int mt = 0; mt < 4; mt++)
        #pragma unroll
        for (int nt = 0; nt < 4; nt++)
            #pragma unroll
            for (int e = 0; e < 4; e++) acc[mt][nt][e] = 0.f;

    #pragma unroll
    for (int kk = 0; kk < 8; kk++) {
        uint32_t a[4][4];
        #pragma unroll
        for (int mt = 0; mt < 4; mt++) {
            uint32_t addr = es_base +
                4u * ((mt * 16 + (lane & 7) + (g & 1) * 8) * 68 + kk * 8 + (g >> 1) * 4);
            ldsm_x4(a[mt][0], a[mt][1], a[mt][2], a[mt][3], addr);
        }
        uint32_t b[4][2];
        #pragma unroll
        for (int nt = 0; nt < 4; nt++) {
            int n = w * 32 + nt * 8 + r;
            b[nt][0] = Ws[n * 68 + kk * 8 + q];
            b[nt][1] = Ws[n * 68 + kk * 8 + 4 + q];
        }
        #pragma unroll
        for (int mt = 0; mt < 4; mt++)
            #pragma unroll
            for (int nt = 0; nt < 4; nt++)
                mma16816(acc[mt][nt], a[mt], b[nt][0], b[nt][1]);
    }

    // epilogue: scale + bias, pack bf16x2, store
    uint32_t* qk32 = reinterpret_cast<uint32_t*>(g_qk);
    #pragma unroll
    for (int mt = 0; mt < 4; mt++) {
        #pragma unroll
        for (int nt = 0; nt < 4; nt++) {
            int f0 = w * 32 + nt * 8 + 2 * q;
            float s = (f0 < 64) ? 0.125f : 1.0f;
            float b0v = Bs[f0], b1v = Bs[f0 + 1];
            int vlo = v0 + mt * 16 + r, vhi = vlo + 8;
            if (vlo < V)
                qk32[(size_t)vlo * 64 + (f0 >> 1)] =
                    u2(__floats2bfloat162_rn(acc[mt][nt][0] * s + b0v,
                                             acc[mt][nt][1] * s + b1v));
            if (vhi < V)
                qk32[(size_t)vhi * 64 + (f0 >> 1)] =
                    u2(__floats2bfloat162_rn(acc[mt][nt][2] * s + b0v,
                                             acc[mt][nt][3] * s + b1v));
        }
    }
}

// ------------------------------------------------------------------ K2
// warp = set. sQ/sK rows stride 36 u32 (144B). Scores: m32 n32 k64 -> 32 HMMA.
__global__ void __launch_bounds__(128) concept_kernel(
    const int*   __restrict__ ids,
    const float* __restrict__ mask,
    const float* __restrict__ times,
    const float* __restrict__ emb,
    float*       __restrict__ out,
    int nsets)
{
    __shared__ uint32_t sQ[4][32 * 36];
    __shared__ uint32_t sK[4][32 * 36];
    __shared__ float    sg[4][32];

    const unsigned FULL = 0xffffffffu;
    int warp = threadIdx.x >> 5, lane = threadIdx.x & 31;
    int set  = blockIdx.x * 4 + warp;
    if (set >= nsets) return;

    int   idv = ids[set * NSET + lane];
    float mk  = mask[set * NSET + lane];
    float tm  = times[set];
    float2 tv = g_tm[idv];
    float sig = 1.0f / (1.0f + __expf(-(tv.x - tv.y * tm)));
    float wgt = sig * mk;   // exactly 0 for masked concepts

    // gather QK row -> smem (Q first 128B, K next 128B)
    {
        const uint4* row = reinterpret_cast<const uint4*>(g_qk + (size_t)idv * 128);
        uint4* dq = reinterpret_cast<uint4*>(&sQ[warp][lane * 36]);
        uint4* dk = reinterpret_cast<uint4*>(&sK[warp][lane * 36]);
        #pragma unroll
        for (int c = 0; c < 8; c++) dq[c] = row[c];
        #pragma unroll
        for (int c = 0; c < 8; c++) dk[c] = row[c + 8];
    }
    __syncwarp();

    // S = Q K^T : 2 m-tiles x 4 n-tiles x 4 k-steps
    float acc[2][4][4];
    #pragma unroll
    for (int mt = 0; mt < 2; mt++)
        #pragma unroll
        for (int nt = 0; nt < 4; nt++)
            #pragma unroll
            for (int e = 0; e < 4; e++) acc[mt][nt][e] = 0.f;

    uint32_t qbse = s2u(&sQ[warp][0]);
    uint32_t kbse = s2u(&sK[warp][0]);
    int g = lane >> 3;
    int q = lane & 3, r = lane >> 2;

    #pragma unroll
    for (int kk = 0; kk < 4; kk++) {
        uint32_t a[2][4];
        #pragma unroll
        for (int mt = 0; mt < 2; mt++) {
            uint32_t addr = qbse +
                4u * ((mt * 16 + (lane & 7) + (g & 1) * 8) * 36 + kk * 8 + (g >> 1) * 4);
            ldsm_x4(a[mt][0], a[mt][1], a[mt][2], a[mt][3], addr);
        }
        uint32_t b[4][2];
        #pragma unroll
        for (int p = 0; p < 2; p++) {
            uint32_t t0, t1, t2, t3;
            uint32_t addr = kbse +
                4u * ((p * 16 + (lane & 7) + (g >> 1) * 8) * 36 + kk * 8 + (g & 1) * 4);
            ldsm_x4(t0, t1, t2, t3, addr);
            b[2 * p][0] = t0; b[2 * p][1] = t1;          // n-tile 2p   (k lo / k hi)
            b[2 * p + 1][0] = t2; b[2 * p + 1][1] = t3;  // n-tile 2p+1
        }
        #pragma unroll
        for (int mt = 0; mt < 2; mt++)
            #pragma unroll
            for (int nt = 0; nt < 4; nt++)
                mma16816(acc[mt][nt], a[mt], b[nt][0], b[nt][1]);
    }

    // Row-wise softmax (reference's kmask = m*m^T is 0 on unmasked query rows,
    // so softmax runs over ALL 32 keys; masked query rows are zeroed by wgt=0).
    // Thread holds rows: mt*16 + h*8 + r, cols nt*8 + 2q + b.
    float coef[2][2];
    #pragma unroll
    for (int mt = 0; mt < 2; mt++) {
        #pragma unroll
        for (int h = 0; h < 2; h++) {
            float mx = acc[mt][0][2 * h];
            #pragma unroll
            for (int nt = 0; nt < 4; nt++)
                #pragma unroll
                for (int bb = 0; bb < 2; bb++)
                    mx = fmaxf(mx, acc[mt][nt][2 * h + bb]);
            mx = fmaxf(mx, __shfl_xor_sync(FULL, mx, 1));
            mx = fmaxf(mx, __shfl_xor_sync(FULL, mx, 2));
            float den = 0.f;
            #pragma unroll
            for (int nt = 0; nt < 4; nt++)
                #pragma unroll
                for (int bb = 0; bb < 2; bb++) {
                    float e = __expf(acc[mt][nt][2 * h + bb] - mx);
                    acc[mt][nt][2 * h + bb] = e;
                    den += e;
                }
            den += __shfl_xor_sync(FULL, den, 1);
            den += __shfl_xor_sync(FULL, den, 2);
            int ri = mt * 16 + h * 8 + r;
            float wr = __shfl_sync(FULL, wgt, ri);
            coef[mt][h] = __fdividef(wr, den);
        }
    }

    // g_j = sum_i w_i p_ij : local over 4 row-instances, then stride-4 shfl reduce
    float cs[4][2];
    #pragma unroll
    for (int nt = 0; nt < 4; nt++)
        #pragma unroll
        for (int bb = 0; bb < 2; bb++) {
            float v = acc[0][nt][bb]     * coef[0][0]
                    + acc[0][nt][2 + bb] * coef[0][1]
                    + acc[1][nt][bb]     * coef[1][0]
                    + acc[1][nt][2 + bb] * coef[1][1];
            v += __shfl_xor_sync(FULL, v, 4);
            v += __shfl_xor_sync(FULL, v, 8);
            v += __shfl_xor_sync(FULL, v, 16);
            cs[nt][bb] = v;
        }
    if (r == 0) {   // lanes 0..3 hold complete column sums
        #pragma unroll
        for (int nt = 0; nt < 4; nt++)
            #pragma unroll
            for (int bb = 0; bb < 2; bb++)
                sg[warp][nt * 8 + 2 * q + bb] = cs[nt][bb];
    }
    __syncwarp();

    // pooled_d = sum_j g_j * emb[v_j][d]  (fp32, lane owns 4 dims)
    float4 p = make_float4(0.f, 0.f, 0.f, 0.f);
    #pragma unroll 8
    for (int j = 0; j < NSET; j++) {
        float gj = sg[warp][j];
        int   vj = __shfl_sync(FULL, idv, j);
        float4 e4 = reinterpret_cast<const float4*>(emb + (size_t)vj * 128)[lane];
        p.x = fmaf(gj, e4.x, p.x);
        p.y = fmaf(gj, e4.y, p.y);
        p.z = fmaf(gj, e4.z, p.z);
        p.w = fmaf(gj, e4.w, p.w);
    }
    reinterpret_cast<float4*>(out + (size_t)set * 128)[lane] = p;
}

// ---------------------------------------------------------------- launch
extern "C" void kernel_launch(void* const* d_in, const int* in_sizes, int n_in,
                              void* d_out, int out_size) {
    const int*   ids   = (const int*)  d_in[0];
    const float* mask  = (const float*)d_in[1];
    const float* times = (const float*)d_in[2];
    const float* emb   = (const float*)d_in[3];
    const float* qW    = (const float*)d_in[4];
    const float* qb    = (const float*)d_in[5];
    const float* kW    = (const float*)d_in[6];
    const float* kb    = (const float*)d_in[7];
    const float* theta = (const float*)d_in[8];
    const float* mu    = (const float*)d_in[9];
    float* out = (float*)d_out;

    int nsets = in_sizes[2];          // B*LS
    int V     = in_sizes[8];          // vocab
    if (V > V_MAX) V = V_MAX;

    const int smem = (128 * 68 + 64 * 68) * 4 + 512;   // 52736 B
    cudaFuncSetAttribute(qk_mma, cudaFuncAttributeMaxDynamicSharedMemorySize, smem);
    qk_mma<<<(V + 63) / 64, 128, smem>>>(emb, qW, qb, kW, kb, theta, mu, V);
    concept_kernel<<<(nsets + 3) / 4, 128>>>(ids, mask, times, emb, out, nsets);
}

// round 8
// speedup vs baseline: 2.0253x; 1.3969x over previous
#include <cuda_runtime.h>
#include <cuda_bf16.h>
#include <cstdint>

// ConceptEmb, round 4: coalesced K2 gather (j-loop, warp-cooperative row loads
// into one sQK buffer) to kill the L1 wavefront bottleneck seen in R3 ncu.
//  K1 (qk_mma): unchanged — fused W-prep + QK table GEMM via mma m16n8k16 bf16.
//  K2: warp = set. sQK[32][68 u32]: Q in u32 0..31, K in u32 32..63 per row.
//      Scores via 32 HMMA, softmax in C-fragment layout, column-sum g_j,
//      pooled = sum_j g_j emb[v_j] in fp32.

#define V_MAX 50000
#define NSET  32

__device__ __nv_bfloat16 g_qk[(size_t)V_MAX * 128];
__device__ float2        g_tm[V_MAX];

static __device__ __forceinline__ __nv_bfloat162 b2(uint32_t u) {
    return *reinterpret_cast<__nv_bfloat162*>(&u);
}
static __device__ __forceinline__ uint32_t u2(__nv_bfloat162 h) {
    return *reinterpret_cast<uint32_t*>(&h);
}
static __device__ __forceinline__ uint32_t s2u(const void* p) {
    return (uint32_t)__cvta_generic_to_shared(p);
}
static __device__ __forceinline__ void ldsm_x4(uint32_t& r0, uint32_t& r1,
                                               uint32_t& r2, uint32_t& r3, uint32_t a) {
    asm volatile("ldmatrix.sync.aligned.m8n8.x4.shared.b16 {%0,%1,%2,%3}, [%4];"
                 : "=r"(r0), "=r"(r1), "=r"(r2), "=r"(r3) : "r"(a));
}
static __device__ __forceinline__ void mma16816(float* c,
        const uint32_t* a, uint32_t b0, uint32_t b1) {
    asm volatile("mma.sync.aligned.m16n8k16.row.col.f32.bf16.bf16.f32 "
                 "{%0,%1,%2,%3}, {%4,%5,%6,%7}, {%8,%9}, {%0,%1,%2,%3};"
                 : "+f"(c[0]), "+f"(c[1]), "+f"(c[2]), "+f"(c[3])
                 : "r"(a[0]), "r"(a[1]), "r"(a[2]), "r"(a[3]), "r"(b0), "r"(b1));
}

// ------------------------------------------------------------------ K1
__global__ void __launch_bounds__(128) qk_mma(
    const float* __restrict__ emb,
    const float* __restrict__ qW, const float* __restrict__ qb,
    const float* __restrict__ kW, const float* __restrict__ kb,
    const float* __restrict__ theta, const float* __restrict__ mu, int V)
{
    extern __shared__ uint32_t dsm[];
    uint32_t* Ws = dsm;                 // 128*68 u32
    uint32_t* Es = dsm + 128 * 68;      // 64*68 u32
    float*    Bs = (float*)(dsm + 128 * 68 + 64 * 68);  // 128 f32

    int tid = threadIdx.x, lane = tid & 31, w = tid >> 5;
    int v0 = blockIdx.x * 64;

    for (int i = tid; i < 64 * 128; i += 128) {
        int f = i >> 6, dp = i & 63;
        const float* src = (f < 64) ? (qW + f * 128) : (kW + (f - 64) * 128);
        float2 v = *reinterpret_cast<const float2*>(src + dp * 2);
        Ws[f * 68 + dp] = u2(__floats2bfloat162_rn(v.x, v.y));
    }
    Bs[tid] = (tid < 64) ? qb[tid] * 0.125f : kb[tid - 64];
    for (int i = tid; i < 32 * 128; i += 128) {
        int r = i >> 6, dp = i & 63;
        int v = v0 + r;
        float2 e = make_float2(0.f, 0.f);
        if (v < V) e = *reinterpret_cast<const float2*>(emb + (size_t)v * 128 + dp * 2);
        Es[r * 68 + dp] = u2(__floats2bfloat162_rn(e.x, e.y));
    }
    if (tid < 64 && (v0 + tid) < V)
        g_tm[v0 + tid] = make_float2(theta[v0 + tid], mu[v0 + tid]);
    __syncthreads();

    uint32_t es_base = s2u(Es);
    int g = lane >> 3;
    int q = lane & 3, r = lane >> 2;

    float acc[4][4][4];
    #pragma unroll
    for (int mt = 0; mt < 4; mt++)
        #pragma unroll
        for (int nt = 0; nt < 4; nt++)
            #pragma unroll
            for (int e = 0; e < 4; e++) acc[mt][nt][e] = 0.f;

    #pragma unroll
    for (int kk = 0; kk < 8; kk++) {
        uint32_t a[4][4];
        #pragma unroll
        for (int mt = 0; mt < 4; mt++) {
            uint32_t addr = es_base +
                4u * ((mt * 16 + (lane & 7) + (g & 1) * 8) * 68 + kk * 8 + (g >> 1) * 4);
            ldsm_x4(a[mt][0], a[mt][1], a[mt][2], a[mt][3], addr);
        }
        uint32_t b[4][2];
        #pragma unroll
        for (int nt = 0; nt < 4; nt++) {
            int n = w * 32 + nt * 8 + r;
            b[nt][0] = Ws[n * 68 + kk * 8 + q];
            b[nt][1] = Ws[n * 68 + kk * 8 + 4 + q];
        }
        #pragma unroll
        for (int mt = 0; mt < 4; mt++)
            #pragma unroll
            for (int nt = 0; nt < 4; nt++)
                mma16816(acc[mt][nt], a[mt], b[nt][0], b[nt][1]);
    }

    uint32_t* qk32 = reinterpret_cast<uint32_t*>(g_qk);
    #pragma unroll
    for (int mt = 0; mt < 4; mt++) {
        #pragma unroll
        for (int nt = 0; nt < 4; nt++) {
            int f0 = w * 32 + nt * 8 + 2 * q;
            float s = (f0 < 64) ? 0.125f : 1.0f;
            float b0v = Bs[f0], b1v = Bs[f0 + 1];
            int vlo = v0 + mt * 16 + r, vhi = vlo + 8;
            if (vlo < V)
                qk32[(size_t)vlo * 64 + (f0 >> 1)] =
                    u2(__floats2bfloat162_rn(acc[mt][nt][0] * s + b0v,
                                             acc[mt][nt][1] * s + b1v));
            if (vhi < V)
                qk32[(size_t)vhi * 64 + (f0 >> 1)] =
                    u2(__floats2bfloat162_rn(acc[mt][nt][2] * s + b0v,
                                             acc[mt][nt][3] * s + b1v));
        }
    }
}

// ------------------------------------------------------------------ K2
// warp = set. sQK rows stride 68 u32 (272B): Q = u32 [0,32), K = u32 [32,64).
__global__ void __launch_bounds__(128) concept_kernel(
    const int*   __restrict__ ids,
    const float* __restrict__ mask,
    const float* __restrict__ times,
    const float* __restrict__ emb,
    float*       __restrict__ out,
    int nsets)
{
    __shared__ __align__(16) uint32_t sQK[4][32 * 68];
    __shared__ float sg[4][32];

    const unsigned FULL = 0xffffffffu;
    int warp = threadIdx.x >> 5, lane = threadIdx.x & 31;
    int set  = blockIdx.x * 4 + warp;
    if (set >= nsets) return;

    int   idv = ids[set * NSET + lane];
    float mk  = mask[set * NSET + lane];
    float tm  = times[set];
    float2 tv = g_tm[idv];
    float sig = 1.0f / (1.0f + __expf(-(tv.x - tv.y * tm)));
    float wgt = sig * mk;   // exactly 0 for masked concepts

    // Coalesced gather: warp loads concept j's 256B QK row together.
    const char* qkb = reinterpret_cast<const char*>(g_qk);
    #pragma unroll 4
    for (int j = 0; j < NSET; j++) {
        int vj = __shfl_sync(FULL, idv, j);
        uint2 d = *reinterpret_cast<const uint2*>(qkb + (size_t)vj * 256 + lane * 8);
        *reinterpret_cast<uint2*>(&sQK[warp][j * 68 + lane * 2]) = d;
    }
    __syncwarp();

    // S = Q K^T : 2 m-tiles x 4 n-tiles x 4 k-steps (32 HMMA)
    float acc[2][4][4];
    #pragma unroll
    for (int mt = 0; mt < 2; mt++)
        #pragma unroll
        for (int nt = 0; nt < 4; nt++)
            #pragma unroll
            for (int e = 0; e < 4; e++) acc[mt][nt][e] = 0.f;

    uint32_t base = s2u(&sQK[warp][0]);
    int g = lane >> 3;
    int q = lane & 3, r = lane >> 2;

    #pragma unroll
    for (int kk = 0; kk < 4; kk++) {
        uint32_t a[2][4];
        #pragma unroll
        for (int mt = 0; mt < 2; mt++) {
            uint32_t addr = base +
                4u * ((mt * 16 + (lane & 7) + (g & 1) * 8) * 68 + kk * 8 + (g >> 1) * 4);
            ldsm_x4(a[mt][0], a[mt][1], a[mt][2], a[mt][3], addr);
        }
        uint32_t b[4][2];
        #pragma unroll
        for (int p = 0; p < 2; p++) {
            uint32_t t0, t1, t2, t3;
            uint32_t addr = base +
                4u * ((p * 16 + (lane & 7) + (g >> 1) * 8) * 68 + 32 + kk * 8 + (g & 1) * 4);
            ldsm_x4(t0, t1, t2, t3, addr);
            b[2 * p][0] = t0; b[2 * p][1] = t1;
            b[2 * p + 1][0] = t2; b[2 * p + 1][1] = t3;
        }
        #pragma unroll
        for (int mt = 0; mt < 2; mt++)
            #pragma unroll
            for (int nt = 0; nt < 4; nt++)
                mma16816(acc[mt][nt], a[mt], b[nt][0], b[nt][1]);
    }

    // Row softmax over ALL 32 keys (kmask = m*m^T is 0 on unmasked query rows;
    // masked query rows die via wgt=0). Rows: mt*16+h*8+r, cols: nt*8+2q+bb.
    float coef[2][2];
    #pragma unroll
    for (int mt = 0; mt < 2; mt++) {
        #pragma unroll
        for (int h = 0; h < 2; h++) {
            float mx = acc[mt][0][2 * h];
            #pragma unroll
            for (int nt = 0; nt < 4; nt++)
                #pragma unroll
                for (int bb = 0; bb < 2; bb++)
                    mx = fmaxf(mx, acc[mt][nt][2 * h + bb]);
            mx = fmaxf(mx, __shfl_xor_sync(FULL, mx, 1));
            mx = fmaxf(mx, __shfl_xor_sync(FULL, mx, 2));
            float den = 0.f;
            #pragma unroll
            for (int nt = 0; nt < 4; nt++)
                #pragma unroll
                for (int bb = 0; bb < 2; bb++) {
                    float e = __expf(acc[mt][nt][2 * h + bb] - mx);
                    acc[mt][nt][2 * h + bb] = e;
                    den += e;
                }
            den += __shfl_xor_sync(FULL, den, 1);
            den += __shfl_xor_sync(FULL, den, 2);
            int ri = mt * 16 + h * 8 + r;
            float wr = __shfl_sync(FULL, wgt, ri);
            coef[mt][h] = __fdividef(wr, den);
        }
    }

    // g_j = sum_i w_i p_ij (column sums via stride-4 shfl reduce)
    float cs[4][2];
    #pragma unroll
    for (int nt = 0; nt < 4; nt++)
        #pragma unroll
        for (int bb = 0; bb < 2; bb++) {
            float v = acc[0][nt][bb]     * coef[0][0]
                    + acc[0][nt][2 + bb] * coef[0][1]
                    + acc[1][nt][bb]     * coef[1][0]
                    + acc[1][nt][2 + bb] * coef[1][1];
            v += __shfl_xor_sync(FULL, v, 4);
            v += __shfl_xor_sync(FULL, v, 8);
            v += __shfl_xor_sync(FULL, v, 16);
            cs[nt][bb] = v;
        }
    if (r == 0) {
        #pragma unroll
        for (int nt = 0; nt < 4; nt++)
            #pragma unroll
            for (int bb = 0; bb < 2; bb++)
                sg[warp][nt * 8 + 2 * q + bb] = cs[nt][bb];
    }
    __syncwarp();

    // pooled_d = sum_j g_j * emb[v_j][d]  (fp32; coalesced float4 rows)
    float4 p = make_float4(0.f, 0.f, 0.f, 0.f);
    #pragma unroll 8
    for (int j = 0; j < NSET; j++) {
        float gj = sg[warp][j];
        int   vj = __shfl_sync(FULL, idv, j);
        float4 e4 = reinterpret_cast<const float4*>(emb + (size_t)vj * 128)[lane];
        p.x = fmaf(gj, e4.x, p.x);
        p.y = fmaf(gj, e4.y, p.y);
        p.z = fmaf(gj, e4.z, p.z);
        p.w = fmaf(gj, e4.w, p.w);
    }
    reinterpret_cast<float4*>(out + (size_t)set * 128)[lane] = p;
}

// ---------------------------------------------------------------- launch
extern "C" void kernel_launch(void* const* d_in, const int* in_sizes, int n_in,
                              void* d_out, int out_size) {
    const int*   ids   = (const int*)  d_in[0];
    const float* mask  = (const float*)d_in[1];
    const float* times = (const float*)d_in[2];
    const float* emb   = (const float*)d_in[3];
    const float* qW    = (const float*)d_in[4];
    const float* qb    = (const float*)d_in[5];
    const float* kW    = (const float*)d_in[6];
    const float* kb    = (const float*)d_in[7];
    const float* theta = (const float*)d_in[8];
    const float* mu    = (const float*)d_in[9];
    float* out = (float*)d_out;

    int nsets = in_sizes[2];
    int V     = in_sizes[8];
    if (V > V_MAX) V = V_MAX;

    const int smem = (128 * 68 + 64 * 68) * 4 + 512;   // 52736 B
    cudaFuncSetAttribute(qk_mma, cudaFuncAttributeMaxDynamicSharedMemorySize, smem);
    qk_mma<<<(V + 63) / 64, 128, smem>>>(emb, qW, qb, kW, kb, theta, mu, V);
    concept_kernel<<<(nsets + 3) / 4, 128>>>(ids, mask, times, emb, out, nsets);
}

// round 9
// speedup vs baseline: 2.3231x; 1.1470x over previous
#include <cuda_runtime.h>
#include <cuda_bf16.h>
#include <cstdint>

// ConceptEmb, round 8: K2 gather via cp.async.cg (LDGSTS) — kill the exposed
// LDG->STS latency identified in R7 ncu (latency-bound: no pipe saturated).
//  K1 (qk_mma): unchanged — fused W-prep + QK table GEMM via mma m16n8k16 bf16.
//  K2: warp = set. sQK[32][68 u32]: Q in u32 0..31, K in u32 32..63 per row.
//      Gather: 16x cp.async.cg 16B (2 rows/instr), one wait at the end.
//      Scores via 32 HMMA, softmax in C-fragment layout, column-sum g_j,
//      pooled = sum_j g_j emb[v_j] in fp32.

#define V_MAX 50000
#define NSET  32

__device__ __nv_bfloat16 g_qk[(size_t)V_MAX * 128];
__device__ float2        g_tm[V_MAX];

static __device__ __forceinline__ __nv_bfloat162 b2(uint32_t u) {
    return *reinterpret_cast<__nv_bfloat162*>(&u);
}
static __device__ __forceinline__ uint32_t u2(__nv_bfloat162 h) {
    return *reinterpret_cast<uint32_t*>(&h);
}
static __device__ __forceinline__ uint32_t s2u(const void* p) {
    return (uint32_t)__cvta_generic_to_shared(p);
}
static __device__ __forceinline__ void ldsm_x4(uint32_t& r0, uint32_t& r1,
                                               uint32_t& r2, uint32_t& r3, uint32_t a) {
    asm volatile("ldmatrix.sync.aligned.m8n8.x4.shared.b16 {%0,%1,%2,%3}, [%4];"
                 : "=r"(r0), "=r"(r1), "=r"(r2), "=r"(r3) : "r"(a));
}
static __device__ __forceinline__ void mma16816(float* c,
        const uint32_t* a, uint32_t b0, uint32_t b1) {
    asm volatile("mma.sync.aligned.m16n8k16.row.col.f32.bf16.bf16.f32 "
                 "{%0,%1,%2,%3}, {%4,%5,%6,%7}, {%8,%9}, {%0,%1,%2,%3};"
                 : "+f"(c[0]), "+f"(c[1]), "+f"(c[2]), "+f"(c[3])
                 : "r"(a[0]), "r"(a[1]), "r"(a[2]), "r"(a[3]), "r"(b0), "r"(b1));
}
static __device__ __forceinline__ void cp16(uint32_t smem_addr, const void* gptr) {
    asm volatile("cp.async.cg.shared.global [%0], [%1], 16;"
                 :: "r"(smem_addr), "l"(gptr));
}

// ------------------------------------------------------------------ K1
__global__ void __launch_bounds__(128) qk_mma(
    const float* __restrict__ emb,
    const float* __restrict__ qW, const float* __restrict__ qb,
    const float* __restrict__ kW, const float* __restrict__ kb,
    const float* __restrict__ theta, const float* __restrict__ mu, int V)
{
    extern __shared__ uint32_t dsm[];
    uint32_t* Ws = dsm;                 // 128*68 u32
    uint32_t* Es = dsm + 128 * 68;      // 64*68 u32
    float*    Bs = (float*)(dsm + 128 * 68 + 64 * 68);  // 128 f32

    int tid = threadIdx.x, lane = tid & 31, w = tid >> 5;
    int v0 = blockIdx.x * 64;

    for (int i = tid; i < 64 * 128; i += 128) {
        int f = i >> 6, dp = i & 63;
        const float* src = (f < 64) ? (qW + f * 128) : (kW + (f - 64) * 128);
        float2 v = *reinterpret_cast<const float2*>(src + dp * 2);
        Ws[f * 68 + dp] = u2(__floats2bfloat162_rn(v.x, v.y));
    }
    Bs[tid] = (tid < 64) ? qb[tid] * 0.125f : kb[tid - 64];
    for (int i = tid; i < 32 * 128; i += 128) {
        int r = i >> 6, dp = i & 63;
        int v = v0 + r;
        float2 e = make_float2(0.f, 0.f);
        if (v < V) e = *reinterpret_cast<const float2*>(emb + (size_t)v * 128 + dp * 2);
        Es[r * 68 + dp] = u2(__floats2bfloat162_rn(e.x, e.y));
    }
    if (tid < 64 && (v0 + tid) < V)
        g_tm[v0 + tid] = make_float2(theta[v0 + tid], mu[v0 + tid]);
    __syncthreads();

    uint32_t es_base = s2u(Es);
    int g = lane >> 3;
    int q = lane & 3, r = lane >> 2;

    float acc[4][4][4];
    #pragma unroll
    for (int mt = 0; mt < 4; mt++)
        #pragma unroll
        for (int nt = 0; nt < 4; nt++)
            #pragma unroll
            for (int e = 0; e < 4; e++) acc[mt][nt][e] = 0.f;

    #pragma unroll
    for (int kk = 0; kk < 8; kk++) {
        uint32_t a[4][4];
        #pragma unroll
        for (int mt = 0; mt < 4; mt++) {
            uint32_t addr = es_base +
                4u * ((mt * 16 + (lane & 7) + (g & 1) * 8) * 68 + kk * 8 + (g >> 1) * 4);
            ldsm_x4(a[mt][0], a[mt][1], a[mt][2], a[mt][3], addr);
        }
        uint32_t b[4][2];
        #pragma unroll
        for (int nt = 0; nt < 4; nt++) {
            int n = w * 32 + nt * 8 + r;
            b[nt][0] = Ws[n * 68 + kk * 8 + q];
            b[nt][1] = Ws[n * 68 + kk * 8 + 4 + q];
        }
        #pragma unroll
        for (int mt = 0; mt < 4; mt++)
            #pragma unroll
            for (int nt = 0; nt < 4; nt++)
                mma16816(acc[mt][nt], a[mt], b[nt][0], b[nt][1]);
    }

    uint32_t* qk32 = reinterpret_cast<uint32_t*>(g_qk);
    #pragma unroll
    for (int mt = 0; mt < 4; mt++) {
        #pragma unroll
        for (int nt = 0; nt < 4; nt++) {
            int f0 = w * 32 + nt * 8 + 2 * q;
            float s = (f0 < 64) ? 0.125f : 1.0f;
            float b0v = Bs[f0], b1v = Bs[f0 + 1];
            int vlo = v0 + mt * 16 + r, vhi = vlo + 8;
            if (vlo < V)
                qk32[(size_t)vlo * 64 + (f0 >> 1)] =
                    u2(__floats2bfloat162_rn(acc[mt][nt][0] * s + b0v,
                                             acc[mt][nt][1] * s + b1v));
            if (vhi < V)
                qk32[(size_t)vhi * 64 + (f0 >> 1)] =
                    u2(__floats2bfloat162_rn(acc[mt][nt][2] * s + b0v,
                                             acc[mt][nt][3] * s + b1v));
        }
    }
}

// ------------------------------------------------------------------ K2
// warp = set. sQK rows stride 68 u32 (272B): Q = u32 [0,32), K = u32 [32,64).
__global__ void __launch_bounds__(128) concept_kernel(
    const int*   __restrict__ ids,
    const float* __restrict__ mask,
    const float* __restrict__ times,
    const float* __restrict__ emb,
    float*       __restrict__ out,
    int nsets)
{
    __shared__ __align__(16) uint32_t sQK[4][32 * 68];
    __shared__ float sg[4][32];

    const unsigned FULL = 0xffffffffu;
    int warp = threadIdx.x >> 5, lane = threadIdx.x & 31;
    int set  = blockIdx.x * 4 + warp;
    if (set >= nsets) return;

    int   idv = ids[set * NSET + lane];

    // Gather all 32 QK rows via cp.async.cg: 2 rows per instruction
    // (lanes 0-15 -> row j, lanes 16-31 -> row j+1), 16B per lane.
    {
        const char* qkb = reinterpret_cast<const char*>(g_qk);
        int half = lane >> 4, sub = lane & 15;
        uint32_t sbase = s2u(&sQK[warp][0]);
        #pragma unroll
        for (int j = 0; j < NSET; j += 2) {
            int row = j + half;
            int vj  = __shfl_sync(FULL, idv, row);
            cp16(sbase + 4u * (row * 68 + sub * 4),
                 qkb + (size_t)vj * 256 + sub * 16);
        }
        asm volatile("cp.async.commit_group;");
    }

    float mk  = mask[set * NSET + lane];
    float tm  = times[set];
    float2 tv = g_tm[idv];
    float sig = 1.0f / (1.0f + __expf(-(tv.x - tv.y * tm)));
    float wgt = sig * mk;   // exactly 0 for masked concepts

    asm volatile("cp.async.wait_group 0;");
    __syncwarp();

    // S = Q K^T : 2 m-tiles x 4 n-tiles x 4 k-steps (32 HMMA)
    float acc[2][4][4];
    #pragma unroll
    for (int mt = 0; mt < 2; mt++)
        #pragma unroll
        for (int nt = 0; nt < 4; nt++)
            #pragma unroll
            for (int e = 0; e < 4; e++) acc[mt][nt][e] = 0.f;

    uint32_t base = s2u(&sQK[warp][0]);
    int g = lane >> 3;
    int q = lane & 3, r = lane >> 2;

    #pragma unroll
    for (int kk = 0; kk < 4; kk++) {
        uint32_t a[2][4];
        #pragma unroll
        for (int mt = 0; mt < 2; mt++) {
            uint32_t addr = base +
                4u * ((mt * 16 + (lane & 7) + (g & 1) * 8) * 68 + kk * 8 + (g >> 1) * 4);
            ldsm_x4(a[mt][0], a[mt][1], a[mt][2], a[mt][3], addr);
        }
        uint32_t b[4][2];
        #pragma unroll
        for (int p = 0; p < 2; p++) {
            uint32_t t0, t1, t2, t3;
            uint32_t addr = base +
                4u * ((p * 16 + (lane & 7) + (g >> 1) * 8) * 68 + 32 + kk * 8 + (g & 1) * 4);
            ldsm_x4(t0, t1, t2, t3, addr);
            b[2 * p][0] = t0; b[2 * p][1] = t1;
            b[2 * p + 1][0] = t2; b[2 * p + 1][1] = t3;
        }
        #pragma unroll
        for (int mt = 0; mt < 2; mt++)
            #pragma unroll
            for (int nt = 0; nt < 4; nt++)
                mma16816(acc[mt][nt], a[mt], b[nt][0], b[nt][1]);
    }

    // Row softmax over ALL 32 keys (kmask = m*m^T is 0 on unmasked query rows;
    // masked query rows die via wgt=0). Rows: mt*16+h*8+r, cols: nt*8+2q+bb.
    float coef[2][2];
    #pragma unroll
    for (int mt = 0; mt < 2; mt++) {
        #pragma unroll
        for (int h = 0; h < 2; h++) {
            float mx = acc[mt][0][2 * h];
            #pragma unroll
            for (int nt = 0; nt < 4; nt++)
                #pragma unroll
                for (int bb = 0; bb < 2; bb++)
                    mx = fmaxf(mx, acc[mt][nt][2 * h + bb]);
            mx = fmaxf(mx, __shfl_xor_sync(FULL, mx, 1));
            mx = fmaxf(mx, __shfl_xor_sync(FULL, mx, 2));
            float den = 0.f;
            #pragma unroll
            for (int nt = 0; nt < 4; nt++)
                #pragma unroll
                for (int bb = 0; bb < 2; bb++) {
                    float e = __expf(acc[mt][nt][2 * h + bb] - mx);
                    acc[mt][nt][2 * h + bb] = e;
                    den += e;
                }
            den += __shfl_xor_sync(FULL, den, 1);
            den += __shfl_xor_sync(FULL, den, 2);
            int ri = mt * 16 + h * 8 + r;
            float wr = __shfl_sync(FULL, wgt, ri);
            coef[mt][h] = __fdividef(wr, den);
        }
    }

    // g_j = sum_i w_i p_ij (column sums via stride-4 shfl reduce)
    float cs[4][2];
    #pragma unroll
    for (int nt = 0; nt < 4; nt++)
        #pragma unroll
        for (int bb = 0; bb < 2; bb++) {
            float v = acc[0][nt][bb]     * coef[0][0]
                    + acc[0][nt][2 + bb] * coef[0][1]
                    + acc[1][nt][bb]     * coef[1][0]
                    + acc[1][nt][2 + bb] * coef[1][1];
            v += __shfl_xor_sync(FULL, v, 4);
            v += __shfl_xor_sync(FULL, v, 8);
            v += __shfl_xor_sync(FULL, v, 16);
            cs[nt][bb] = v;
        }
    if (r == 0) {
        #pragma unroll
        for (int nt = 0; nt < 4; nt++)
            #pragma unroll
            for (int bb = 0; bb < 2; bb++)
                sg[warp][nt * 8 + 2 * q + bb] = cs[nt][bb];
    }
    __syncwarp();

    // pooled_d = sum_j g_j * emb[v_j][d]  (fp32; coalesced float4 rows)
    float4 p = make_float4(0.f, 0.f, 0.f, 0.f);
    #pragma unroll 8
    for (int j = 0; j < NSET; j++) {
        float gj = sg[warp][j];
        int   vj = __shfl_sync(FULL, idv, j);
        float4 e4 = reinterpret_cast<const float4*>(emb + (size_t)vj * 128)[lane];
        p.x = fmaf(gj, e4.x, p.x);
        p.y = fmaf(gj, e4.y, p.y);
        p.z = fmaf(gj, e4.z, p.z);
        p.w = fmaf(gj, e4.w, p.w);
    }
    reinterpret_cast<float4*>(out + (size_t)set * 128)[lane] = p;
}

// ---------------------------------------------------------------- launch
extern "C" void kernel_launch(void* const* d_in, const int* in_sizes, int n_in,
                              void* d_out, int out_size) {
    const int*   ids   = (const int*)  d_in[0];
    const float* mask  = (const float*)d_in[1];
    const float* times = (const float*)d_in[2];
    const float* emb   = (const float*)d_in[3];
    const float* qW    = (const float*)d_in[4];
    const float* qb    = (const float*)d_in[5];
    const float* kW    = (const float*)d_in[6];
    const float* kb    = (const float*)d_in[7];
    const float* theta = (const float*)d_in[8];
    const float* mu    = (const float*)d_in[9];
    float* out = (float*)d_out;

    int nsets = in_sizes[2];
    int V     = in_sizes[8];
    if (V > V_MAX) V = V_MAX;

    const int smem = (128 * 68 + 64 * 68) * 4 + 512;   // 52736 B
    cudaFuncSetAttribute(qk_mma, cudaFuncAttributeMaxDynamicSharedMemorySize, smem);
    qk_mma<<<(V + 63) / 64, 128, smem>>>(emb, qW, qb, kW, kb, theta, mu, V);
    concept_kernel<<<(nsets + 3) / 4, 128>>>(ids, mask, times, emb, out, nsets);
}

// round 11
// speedup vs baseline: 2.4147x; 1.0394x over previous
#include <cuda_runtime.h>
#include <cuda_bf16.h>
#include <cuda_fp16.h>
#include <cstdint>

// ConceptEmb, round 10 (resubmit of audited R9 — infra failure last round):
//  (a) pooling reads fp16 emb copy g_eb (built in K1) — 33% less K2 traffic.
//  (b) sQK XOR-swizzled (no padding) -> 32KB smem/CTA + sg reuse + lb(128,7)
//      -> 7 CTAs/SM (occ 33.7% -> ~43%).
//  K1 (qk_mma): fused W-prep + QK table GEMM (mma m16n8k16 bf16) + fp16 emb copy.
//  K2: warp = set. cp.async gather of QK rows, 32 HMMA scores, C-frag softmax,
//      column-sum g_j, pooled = sum_j g_j emb16[v_j] (fp32 accumulate).

#define V_MAX 50000
#define NSET  32

__device__ __nv_bfloat16 g_qk[(size_t)V_MAX * 128];
__device__ uint32_t      g_eb[(size_t)V_MAX * 64];   // fp16x2 emb copy
__device__ float2        g_tm[V_MAX];

static __device__ __forceinline__ __nv_bfloat162 b2(uint32_t u) {
    return *reinterpret_cast<__nv_bfloat162*>(&u);
}
static __device__ __forceinline__ uint32_t u2(__nv_bfloat162 h) {
    return *reinterpret_cast<uint32_t*>(&h);
}
static __device__ __forceinline__ uint32_t s2u(const void* p) {
    return (uint32_t)__cvta_generic_to_shared(p);
}
static __device__ __forceinline__ void ldsm_x4(uint32_t& r0, uint32_t& r1,
                                               uint32_t& r2, uint32_t& r3, uint32_t a) {
    asm volatile("ldmatrix.sync.aligned.m8n8.x4.shared.b16 {%0,%1,%2,%3}, [%4];"
                 : "=r"(r0), "=r"(r1), "=r"(r2), "=r"(r3) : "r"(a));
}
static __device__ __forceinline__ void mma16816(float* c,
        const uint32_t* a, uint32_t b0, uint32_t b1) {
    asm volatile("mma.sync.aligned.m16n8k16.row.col.f32.bf16.bf16.f32 "
                 "{%0,%1,%2,%3}, {%4,%5,%6,%7}, {%8,%9}, {%0,%1,%2,%3};"
                 : "+f"(c[0]), "+f"(c[1]), "+f"(c[2]), "+f"(c[3])
                 : "r"(a[0]), "r"(a[1]), "r"(a[2]), "r"(a[3]), "r"(b0), "r"(b1));
}
static __device__ __forceinline__ void cp16(uint32_t smem_addr, const void* gptr) {
    asm volatile("cp.async.cg.shared.global [%0], [%1], 16;"
                 :: "r"(smem_addr), "l"(gptr));
}

// ------------------------------------------------------------------ K1
__global__ void __launch_bounds__(128) qk_mma(
    const float* __restrict__ emb,
    const float* __restrict__ qW, const float* __restrict__ qb,
    const float* __restrict__ kW, const float* __restrict__ kb,
    const float* __restrict__ theta, const float* __restrict__ mu, int V)
{
    extern __shared__ uint32_t dsm[];
    uint32_t* Ws = dsm;                 // 128*68 u32
    uint32_t* Es = dsm + 128 * 68;      // 64*68 u32
    float*    Bs = (float*)(dsm + 128 * 68 + 64 * 68);  // 128 f32

    int tid = threadIdx.x, lane = tid & 31, w = tid >> 5;
    int v0 = blockIdx.x * 64;

    for (int i = tid; i < 64 * 128; i += 128) {
        int f = i >> 6, dp = i & 63;
        const float* src = (f < 64) ? (qW + f * 128) : (kW + (f - 64) * 128);
        float2 v = *reinterpret_cast<const float2*>(src + dp * 2);
        Ws[f * 68 + dp] = u2(__floats2bfloat162_rn(v.x, v.y));
    }
    Bs[tid] = (tid < 64) ? qb[tid] * 0.125f : kb[tid - 64];
    for (int i = tid; i < 32 * 128; i += 128) {
        int r = i >> 6, dp = i & 63;
        int v = v0 + r;
        float2 e = make_float2(0.f, 0.f);
        if (v < V) {
            e = *reinterpret_cast<const float2*>(emb + (size_t)v * 128 + dp * 2);
            __half2 h = __floats2half2_rn(e.x, e.y);          // fp16 emb copy
            g_eb[(size_t)v * 64 + dp] = *reinterpret_cast<uint32_t*>(&h);
        }
        Es[r * 68 + dp] = u2(__floats2bfloat162_rn(e.x, e.y));
    }
    if (tid < 64 && (v0 + tid) < V)
        g_tm[v0 + tid] = make_float2(theta[v0 + tid], mu[v0 + tid]);
    __syncthreads();

    uint32_t es_base = s2u(Es);
    int g = lane >> 3;
    int q = lane & 3, r = lane >> 2;

    float acc[4][4][4];
    #pragma unroll
    for (int mt = 0; mt < 4; mt++)
        #pragma unroll
        for (int nt = 0; nt < 4; nt++)
            #pragma unroll
            for (int e = 0; e < 4; e++) acc[mt][nt][e] = 0.f;

    #pragma unroll
    for (int kk = 0; kk < 8; kk++) {
        uint32_t a[4][4];
        #pragma unroll
        for (int mt = 0; mt < 4; mt++) {
            uint32_t addr = es_base +
                4u * ((mt * 16 + (lane & 7) + (g & 1) * 8) * 68 + kk * 8 + (g >> 1) * 4);
            ldsm_x4(a[mt][0], a[mt][1], a[mt][2], a[mt][3], addr);
        }
        uint32_t b[4][2];
        #pragma unroll
        for (int nt = 0; nt < 4; nt++) {
            int n = w * 32 + nt * 8 + r;
            b[nt][0] = Ws[n * 68 + kk * 8 + q];
            b[nt][1] = Ws[n * 68 + kk * 8 + 4 + q];
        }
        #pragma unroll
        for (int mt = 0; mt < 4; mt++)
            #pragma unroll
            for (int nt = 0; nt < 4; nt++)
                mma16816(acc[mt][nt], a[mt], b[nt][0], b[nt][1]);
    }

    uint32_t* qk32 = reinterpret_cast<uint32_t*>(g_qk);
    #pragma unroll
    for (int mt = 0; mt < 4; mt++) {
        #pragma unroll
        for (int nt = 0; nt < 4; nt++) {
            int f0 = w * 32 + nt * 8 + 2 * q;
            float s = (f0 < 64) ? 0.125f : 1.0f;
            float b0v = Bs[f0], b1v = Bs[f0 + 1];
            int vlo = v0 + mt * 16 + r, vhi = vlo + 8;
            if (vlo < V)
                qk32[(size_t)vlo * 64 + (f0 >> 1)] =
                    u2(__floats2bfloat162_rn(acc[mt][nt][0] * s + b0v,
                                             acc[mt][nt][1] * s + b1v));
            if (vhi < V)
                qk32[(size_t)vhi * 64 + (f0 >> 1)] =
                    u2(__floats2bfloat162_rn(acc[mt][nt][2] * s + b0v,
                                             acc[mt][nt][3] * s + b1v));
        }
    }
}

// ------------------------------------------------------------------ K2
// warp = set. sQK rows: 64 u32 (256B), 16B atoms XOR-swizzled by (row&7).
// Q = atoms 0..7, K = atoms 8..15.
__global__ void __launch_bounds__(128, 7) concept_kernel(
    const int*   __restrict__ ids,
    const float* __restrict__ mask,
    const float* __restrict__ times,
    float*       __restrict__ out,
    int nsets)
{
    __shared__ __align__(16) uint32_t sQK[4][32 * 64];

    const unsigned FULL = 0xffffffffu;
    int warp = threadIdx.x >> 5, lane = threadIdx.x & 31;
    int set  = blockIdx.x * 4 + warp;
    if (set >= nsets) return;

    int idv = ids[set * NSET + lane];

    // Gather 32 QK rows via cp.async.cg: 2 rows/instr, 16B/lane, swizzled dst.
    {
        const char* qkb = reinterpret_cast<const char*>(g_qk);
        int half = lane >> 4, sub = lane & 15;
        uint32_t sbase = s2u(&sQK[warp][0]);
        #pragma unroll
        for (int j = 0; j < NSET; j += 2) {
            int row = j + half;
            int vj  = __shfl_sync(FULL, idv, row);
            cp16(sbase + 4u * (row * 64 + ((sub ^ (row & 7)) << 2)),
                 qkb + (size_t)vj * 256 + sub * 16);
        }
        asm volatile("cp.async.commit_group;");
    }

    float mk  = mask[set * NSET + lane];
    float tm  = times[set];
    float2 tv = g_tm[idv];
    float sig = 1.0f / (1.0f + __expf(-(tv.x - tv.y * tm)));
    float wgt = sig * mk;   // exactly 0 for masked concepts

    asm volatile("cp.async.wait_group 0;");
    __syncwarp();

    // S = Q K^T : 2 m-tiles x 4 n-tiles x 4 k-steps (32 HMMA)
    float acc[2][4][4];
    #pragma unroll
    for (int mt = 0; mt < 2; mt++)
        #pragma unroll
        for (int nt = 0; nt < 4; nt++)
            #pragma unroll
            for (int e = 0; e < 4; e++) acc[mt][nt][e] = 0.f;

    uint32_t base = s2u(&sQK[warp][0]);
    int g = lane >> 3;
    int q = lane & 3, r = lane >> 2;

    #pragma unroll
    for (int kk = 0; kk < 4; kk++) {
        uint32_t a[2][4];
        #pragma unroll
        for (int mt = 0; mt < 2; mt++) {
            int row  = mt * 16 + (lane & 7) + (g & 1) * 8;
            int atom = kk * 2 + (g >> 1);
            uint32_t addr = base + 4u * (row * 64 + ((atom ^ (row & 7)) << 2));
            ldsm_x4(a[mt][0], a[mt][1], a[mt][2], a[mt][3], addr);
        }
        uint32_t b[4][2];
        #pragma unroll
        for (int p = 0; p < 2; p++) {
            uint32_t t0, t1, t2, t3;
            int row  = p * 16 + (lane & 7) + (g >> 1) * 8;
            int atom = 8 + kk * 2 + (g & 1);
            uint32_t addr = base + 4u * (row * 64 + ((atom ^ (row & 7)) << 2));
            ldsm_x4(t0, t1, t2, t3, addr);
            b[2 * p][0] = t0; b[2 * p][1] = t1;
            b[2 * p + 1][0] = t2; b[2 * p + 1][1] = t3;
        }
        #pragma unroll
        for (int mt = 0; mt < 2; mt++)
            #pragma unroll
            for (int nt = 0; nt < 4; nt++)
                mma16816(acc[mt][nt], a[mt], b[nt][0], b[nt][1]);
    }

    // Row softmax over ALL 32 keys (kmask = m*m^T is 0 on unmasked query rows;
    // masked query rows die via wgt=0). Rows: mt*16+h*8+r, cols: nt*8+2q+bb.
    float coef[2][2];
    #pragma unroll
    for (int mt = 0; mt < 2; mt++) {
        #pragma unroll
        for (int h = 0; h < 2; h++) {
            float mx = acc[mt][0][2 * h];
            #pragma unroll
            for (int nt = 0; nt < 4; nt++)
                #pragma unroll
                for (int bb = 0; bb < 2; bb++)
                    mx = fmaxf(mx, acc[mt][nt][2 * h + bb]);
            mx = fmaxf(mx, __shfl_xor_sync(FULL, mx, 1));
            mx = fmaxf(mx, __shfl_xor_sync(FULL, mx, 2));
            float den = 0.f;
            #pragma unroll
            for (int nt = 0; nt < 4; nt++)
                #pragma unroll
                for (int bb = 0; bb < 2; bb++) {
                    float e = __expf(acc[mt][nt][2 * h + bb] - mx);
                    acc[mt][nt][2 * h + bb] = e;
                    den += e;
                }
            den += __shfl_xor_sync(FULL, den, 1);
            den += __shfl_xor_sync(FULL, den, 2);
            int ri = mt * 16 + h * 8 + r;
            float wr = __shfl_sync(FULL, wgt, ri);
            coef[mt][h] = __fdividef(wr, den);
        }
    }

    // g_j = sum_i w_i p_ij (column sums via stride-4 shfl reduce).
    // sQK is dead after the MMA loop -> reuse its space for the 32 g values.
    float* sg = reinterpret_cast<float*>(&sQK[warp][0]);
    float cs[4][2];
    #pragma unroll
    for (int nt = 0; nt < 4; nt++)
        #pragma unroll
        for (int bb = 0; bb < 2; bb++) {
            float v = acc[0][nt][bb]     * coef[0][0]
                    + acc[0][nt][2 + bb] * coef[0][1]
                    + acc[1][nt][bb]     * coef[1][0]
                    + acc[1][nt][2 + bb] * coef[1][1];
            v += __shfl_xor_sync(FULL, v, 4);
            v += __shfl_xor_sync(FULL, v, 8);
            v += __shfl_xor_sync(FULL, v, 16);
            cs[nt][bb] = v;
        }
    __syncwarp();
    if (r == 0) {
        #pragma unroll
        for (int nt = 0; nt < 4; nt++)
            #pragma unroll
            for (int bb = 0; bb < 2; bb++)
                sg[nt * 8 + 2 * q + bb] = cs[nt][bb];
    }
    __syncwarp();

    // pooled_d = sum_j g_j * emb16[v_j][d]  (fp32 accumulate; 8B/lane loads)
    float4 p = make_float4(0.f, 0.f, 0.f, 0.f);
    #pragma unroll 8
    for (int j = 0; j < NSET; j++) {
        float gj = sg[j];
        int   vj = __shfl_sync(FULL, idv, j);
        uint2 h2 = reinterpret_cast<const uint2*>(g_eb + (size_t)vj * 64)[lane];
        float2 e0 = __half22float2(*reinterpret_cast<__half2*>(&h2.x));
        float2 e1 = __half22float2(*reinterpret_cast<__half2*>(&h2.y));
        p.x = fmaf(gj, e0.x, p.x);
        p.y = fmaf(gj, e0.y, p.y);
        p.z = fmaf(gj, e1.x, p.z);
        p.w = fmaf(gj, e1.y, p.w);
    }
    reinterpret_cast<float4*>(out + (size_t)set * 128)[lane] = p;
}

// ---------------------------------------------------------------- launch
extern "C" void kernel_launch(void* const* d_in, const int* in_sizes, int n_in,
                              void* d_out, int out_size) {
    const int*   ids   = (const int*)  d_in[0];
    const float* mask  = (const float*)d_in[1];
    const float* times = (const float*)d_in[2];
    const float* emb   = (const float*)d_in[3];
    const float* qW    = (const float*)d_in[4];
    const float* qb    = (const float*)d_in[5];
    const float* kW    = (const float*)d_in[6];
    const float* kb    = (const float*)d_in[7];
    const float* theta = (const float*)d_in[8];
    const float* mu    = (const float*)d_in[9];
    float* out = (float*)d_out;

    int nsets = in_sizes[2];
    int V     = in_sizes[8];
    if (V > V_MAX) V = V_MAX;

    const int smem = (128 * 68 + 64 * 68) * 4 + 512;   // 52736 B
    cudaFuncSetAttribute(qk_mma, cudaFuncAttributeMaxDynamicSharedMemorySize, smem);
    qk_mma<<<(V + 63) / 64, 128, smem>>>(emb, qW, qb, kW, kb, theta, mu, V);
    concept_kernel<<<(nsets + 3) / 4, 128>>>(ids, mask, times, out, nsets);
}